// round 2
// baseline (speedup 1.0000x reference)
#include <cuda_runtime.h>
#include <cstdint>

#define N_NODES_MAX 100000
#define FEAT_DIM 64

__device__ int g_counts[N_NODES_MAX];

// Edge kernel: 16 threads per edge. Each thread gathers one float4 of the
// source node's features and RED-adds it into the accumulator (d_out) at the
// destination row. Lane 0 bumps the in-degree counter.
__global__ void __launch_bounds__(256) edge_scatter_kernel(
    const float* __restrict__ feat,
    const int* __restrict__ src_idx,
    const int* __restrict__ dst_idx,
    float* __restrict__ accum,
    int* __restrict__ counts,
    int E, int N)
{
    int t = blockIdx.x * blockDim.x + threadIdx.x;
    int e = t >> 4;
    int lane = t & 15;
    if (e >= E) return;

    int s = src_idx[e];
    int d = dst_idx[e];
    // Defensive: skip malformed indices instead of faulting.
    if ((unsigned)s >= (unsigned)N || (unsigned)d >= (unsigned)N) return;

    if (lane == 0) atomicAdd(&counts[d], 1);

    const float4 v = *reinterpret_cast<const float4*>(feat + (size_t)s * FEAT_DIM + lane * 4);
    float* dst = accum + (size_t)d * FEAT_DIM + lane * 4;
    asm volatile("red.global.add.v4.f32 [%0], {%1,%2,%3,%4};"
                 :: "l"(dst), "f"(v.x), "f"(v.y), "f"(v.z), "f"(v.w)
                 : "memory");
}

// Finalize: out = count>0 ? 2*feat + S/count : feat   (in place over d_out=S)
__global__ void __launch_bounds__(256) finalize_kernel(
    const float* __restrict__ feat,
    float* __restrict__ out,      // holds S on entry
    const int* __restrict__ counts,
    int n_vec4)                   // N * 16
{
    int i = blockIdx.x * blockDim.x + threadIdx.x;
    if (i >= n_vec4) return;
    int node = i >> 4;   // 16 float4 per node row

    int c = counts[node];
    float4 f = reinterpret_cast<const float4*>(feat)[i];
    float4 o;
    if (c > 0) {
        float inv = 1.0f / (float)c;
        float4 s = reinterpret_cast<float4*>(out)[i];
        o.x = 2.0f * f.x + s.x * inv;
        o.y = 2.0f * f.y + s.y * inv;
        o.z = 2.0f * f.z + s.z * inv;
        o.w = 2.0f * f.w + s.w * inv;
    } else {
        o = f;
    }
    reinterpret_cast<float4*>(out)[i] = o;
}

extern "C" void kernel_launch(void* const* d_in, const int* in_sizes, int n_in,
                              void* d_out, int out_size)
{
    const float* feat = (const float*)d_in[0];
    const int* edge_index = (const int*)d_in[1];   // int32 (JAX x64-disabled)

    int N = in_sizes[0] / FEAT_DIM;       // 100000
    int E = in_sizes[1] / 2;              // 1600000
    const int* src_idx = edge_index;
    const int* dst_idx = edge_index + E;

    float* out = (float*)d_out;

    void* counts_ptr = nullptr;
    cudaGetSymbolAddress(&counts_ptr, g_counts);
    int* counts = (int*)counts_ptr;

    // Zero accumulator (d_out) and counts — async, graph-capturable.
    cudaMemsetAsync(d_out, 0, (size_t)out_size * sizeof(float));
    cudaMemsetAsync(counts, 0, (size_t)N * sizeof(int));

    // Scatter-add src features + in-degree counts.
    {
        long long total_threads = (long long)E * 16;
        int block = 256;
        int grid = (int)((total_threads + block - 1) / block);
        edge_scatter_kernel<<<grid, block>>>(feat, src_idx, dst_idx, out, counts, E, N);
    }

    // Finalize.
    {
        int n_vec4 = N * (FEAT_DIM / 4);
        int block = 256;
        int grid = (n_vec4 + block - 1) / block;
        finalize_kernel<<<grid, block>>>(feat, out, counts, n_vec4);
    }
}

// round 3
// speedup vs baseline: 1.2948x; 1.2948x over previous
#include <cuda_runtime.h>
#include <cstdint>

#define N_NODES_MAX 100000
#define E_MAX       1600000
#define FEAT_DIM    64
#define SCAN_BLOCK  1024

__device__ int g_counts [N_NODES_MAX];   // in-degree
__device__ int g_offsets[N_NODES_MAX];   // excl-scan start -> becomes end after scatter
__device__ int g_blocksums[256];
__device__ int g_csr[E_MAX];             // src ids grouped by dest

// 1) histogram of destination indices
__global__ void __launch_bounds__(256) hist_kernel(
    const int* __restrict__ dst_idx, int* __restrict__ counts, int E, int N)
{
    int e = blockIdx.x * blockDim.x + threadIdx.x;
    if (e >= E) return;
    int d = dst_idx[e];
    if ((unsigned)d < (unsigned)N) atomicAdd(&counts[d], 1);
}

// 2) per-block exclusive scan of counts -> offsets, block totals -> blocksums
__global__ void __launch_bounds__(SCAN_BLOCK) scan_block_kernel(
    const int* __restrict__ counts, int* __restrict__ offsets,
    int* __restrict__ blocksums, int n)
{
    __shared__ int sh[SCAN_BLOCK];
    int i = blockIdx.x * SCAN_BLOCK + threadIdx.x;
    int v = (i < n) ? counts[i] : 0;
    sh[threadIdx.x] = v;
    __syncthreads();
    #pragma unroll
    for (int off = 1; off < SCAN_BLOCK; off <<= 1) {
        int t = (threadIdx.x >= off) ? sh[threadIdx.x - off] : 0;
        __syncthreads();
        sh[threadIdx.x] += t;
        __syncthreads();
    }
    int incl = sh[threadIdx.x];
    if (i < n) offsets[i] = incl - v;                 // exclusive
    if (threadIdx.x == SCAN_BLOCK - 1) blocksums[blockIdx.x] = incl;
}

// 3) scan the block sums (single block)
__global__ void __launch_bounds__(SCAN_BLOCK) scan_top_kernel(
    int* __restrict__ blocksums, int nb)
{
    __shared__ int sh[SCAN_BLOCK];
    int v = (threadIdx.x < nb) ? blocksums[threadIdx.x] : 0;
    sh[threadIdx.x] = v;
    __syncthreads();
    #pragma unroll
    for (int off = 1; off < SCAN_BLOCK; off <<= 1) {
        int t = (threadIdx.x >= off) ? sh[threadIdx.x - off] : 0;
        __syncthreads();
        sh[threadIdx.x] += t;
        __syncthreads();
    }
    if (threadIdx.x < nb) blocksums[threadIdx.x] = sh[threadIdx.x] - v;  // exclusive
}

// 4) add block offsets
__global__ void __launch_bounds__(256) scan_add_kernel(
    int* __restrict__ offsets, const int* __restrict__ blocksums, int n)
{
    int i = blockIdx.x * blockDim.x + threadIdx.x;
    if (i < n) offsets[i] += blocksums[i >> 10];
}

// 5) scatter src ids into CSR (offsets become row ends)
__global__ void __launch_bounds__(256) scatter_kernel(
    const int* __restrict__ src_idx, const int* __restrict__ dst_idx,
    int* __restrict__ offsets, int* __restrict__ csr, int E, int N)
{
    int e = blockIdx.x * blockDim.x + threadIdx.x;
    if (e >= E) return;
    int d = dst_idx[e];
    int s = src_idx[e];
    if ((unsigned)d >= (unsigned)N || (unsigned)s >= (unsigned)N) return;
    int pos = atomicAdd(&offsets[d], 1);
    csr[pos] = s;
}

// 6) aggregate + finalize: 16 lanes per dest node, one float4 per lane.
//    out = deg>0 ? 2*feat[node] + sum(feat[src])/deg : feat[node]
__global__ void __launch_bounds__(256) aggregate_kernel(
    const float* __restrict__ feat,
    const int* __restrict__ csr,
    const int* __restrict__ offsets,   // row ends
    const int* __restrict__ counts,    // degrees
    float* __restrict__ out,
    int N)
{
    int t = blockIdx.x * blockDim.x + threadIdx.x;
    int node = t >> 4;
    int lane = t & 15;
    if (node >= N) return;

    int deg = counts[node];
    int end = offsets[node];
    int start = end - deg;

    float4 a0 = {0.f, 0.f, 0.f, 0.f};
    float4 a1 = {0.f, 0.f, 0.f, 0.f};
    int i = start;
    for (; i + 1 < end; i += 2) {
        int s0 = csr[i];
        int s1 = csr[i + 1];
        float4 v0 = *reinterpret_cast<const float4*>(feat + (size_t)s0 * FEAT_DIM + lane * 4);
        float4 v1 = *reinterpret_cast<const float4*>(feat + (size_t)s1 * FEAT_DIM + lane * 4);
        a0.x += v0.x; a0.y += v0.y; a0.z += v0.z; a0.w += v0.w;
        a1.x += v1.x; a1.y += v1.y; a1.z += v1.z; a1.w += v1.w;
    }
    if (i < end) {
        int s0 = csr[i];
        float4 v0 = *reinterpret_cast<const float4*>(feat + (size_t)s0 * FEAT_DIM + lane * 4);
        a0.x += v0.x; a0.y += v0.y; a0.z += v0.z; a0.w += v0.w;
    }

    float4 f = *reinterpret_cast<const float4*>(feat + (size_t)node * FEAT_DIM + lane * 4);
    float4 o;
    if (deg > 0) {
        float inv = 1.0f / (float)deg;
        o.x = 2.0f * f.x + (a0.x + a1.x) * inv;
        o.y = 2.0f * f.y + (a0.y + a1.y) * inv;
        o.z = 2.0f * f.z + (a0.z + a1.z) * inv;
        o.w = 2.0f * f.w + (a0.w + a1.w) * inv;
    } else {
        o = f;
    }
    *reinterpret_cast<float4*>(out + (size_t)node * FEAT_DIM + lane * 4) = o;
}

extern "C" void kernel_launch(void* const* d_in, const int* in_sizes, int n_in,
                              void* d_out, int out_size)
{
    const float* feat = (const float*)d_in[0];
    const int* edge_index = (const int*)d_in[1];   // int32 (JAX x64-disabled)

    int N = in_sizes[0] / FEAT_DIM;       // 100000
    int E = in_sizes[1] / 2;              // 1600000
    const int* src_idx = edge_index;
    const int* dst_idx = edge_index + E;

    float* out = (float*)d_out;

    void *counts_p, *offsets_p, *blocksums_p, *csr_p;
    cudaGetSymbolAddress(&counts_p,    g_counts);
    cudaGetSymbolAddress(&offsets_p,   g_offsets);
    cudaGetSymbolAddress(&blocksums_p, g_blocksums);
    cudaGetSymbolAddress(&csr_p,       g_csr);
    int* counts    = (int*)counts_p;
    int* offsets   = (int*)offsets_p;
    int* blocksums = (int*)blocksums_p;
    int* csr       = (int*)csr_p;

    // zero degree counters
    cudaMemsetAsync(counts, 0, (size_t)N * sizeof(int));

    // 1) histogram
    hist_kernel<<<(E + 255) / 256, 256>>>(dst_idx, counts, E, N);

    // 2-4) exclusive scan counts -> offsets
    int nblocks = (N + SCAN_BLOCK - 1) / SCAN_BLOCK;   // 98
    scan_block_kernel<<<nblocks, SCAN_BLOCK>>>(counts, offsets, blocksums, N);
    scan_top_kernel<<<1, SCAN_BLOCK>>>(blocksums, nblocks);
    scan_add_kernel<<<(N + 255) / 256, 256>>>(offsets, blocksums, N);

    // 5) scatter src ids by dest
    scatter_kernel<<<(E + 255) / 256, 256>>>(src_idx, dst_idx, offsets, csr, E, N);

    // 6) aggregate + finalize
    {
        long long total = (long long)N * 16;
        int grid = (int)((total + 255) / 256);
        aggregate_kernel<<<grid, 256>>>(feat, csr, offsets, counts, out, N);
    }
}